// round 5
// baseline (speedup 1.0000x reference)
#include <cuda_runtime.h>
#include <math.h>

#define NPROTO  10
#define NCLS    10
#define NPATCH  196
#define NFEAT   1960
#define BIMG    8192
#define NCHUNK  16
#define NGRP    256      // image groups of 32 (one warp-width)

typedef unsigned long long u64;

// scratch: [chunk][group][class][lane]  (floats)
__device__ float g_scratch[NCHUNK * NGRP * NCLS * 32];   // 5.24 MB

// ---- packed f32x2 helpers ---------------------------------------------------
__device__ __forceinline__ u64 pk2(float lo, float hi) {
    u64 r; asm("mov.b64 %0, {%1,%2};" : "=l"(r) : "f"(lo), "f"(hi)); return r;
}
__device__ __forceinline__ u64 fma2(u64 a, u64 b, u64 c) {
    u64 d; asm("fma.rn.f32x2 %0, %1, %2, %3;" : "=l"(d) : "l"(a), "l"(b), "l"(c)); return d;
}
__device__ __forceinline__ u64 mul2(u64 a, u64 b) {
    u64 d; asm("mul.rn.f32x2 %0, %1, %2;" : "=l"(d) : "l"(a), "l"(b)); return d;
}
__device__ __forceinline__ float2 up2(u64 a) {
    float2 f; asm("mov.b64 {%0,%1}, %2;" : "=f"(f.x), "=f"(f.y) : "l"(a)); return f;
}

// ---------------------------------------------------------------------------
// Stage 1: 1024 CTAs x 128. CTA = (chunk, 4 groups). Lane owns ONE image;
// f32x2 packing is over the patch pair (pa, pa+1) which lives in one image
// row (two aligned LDG.128 fetch all 8 pixels). W slice prepacked in smem as
// (W[c,p,pa], W[c,p,pa+1]) u64, classes contiguous -> 5 LDS.128 per (q,p).
// acc[10] u64 only -> low regs -> 6 CTAs/SM (24 warps).
// ---------------------------------------------------------------------------
__global__ void __launch_bounds__(128, 6)
quanv_stage1(const float* __restrict__ x,
             const float* __restrict__ proto,
             const float* __restrict__ W)
{
    __shared__ __align__(16) u64 sWp[7 * NPROTO * NCLS];  // [li][p][c] packed pair
    __shared__ __align__(16) u64 sPc2[NPROTO * 4];        // dup (cy,cy)
    __shared__ __align__(16) u64 sPs2[NPROTO * 4];        // dup (sy,sy)

    const int tid   = threadIdx.x;
    const int chunk = blockIdx.x & 15;
    const int ps = chunk * 6 + min(chunk, 2);   // pair start
    const int np = 6 + (chunk < 2 ? 1 : 0);     // pair count (6 or 7)

    // pack W slice: entry (li,p,c) = (W[c,p,2(ps+li)], W[c,p,2(ps+li)+1])
    for (int i = tid; i < np * 100; i += 128) {
        const int li = i / 100, rem = i - li * 100;
        const int p  = rem / 10, c = rem - p * 10;
        const int pa = 2 * (ps + li);
        float2 wv = *reinterpret_cast<const float2*>(W + c * NFEAT + p * NPATCH + pa);
        sWp[i] = pk2(wv.x, wv.y);
    }
    if (tid < NPROTO * 4) {
        float s, c; __sincosf(0.5f * proto[tid], &s, &c);
        sPc2[tid] = pk2(c, c);
        sPs2[tid] = pk2(s, s);
    }
    __syncthreads();

    const int wid  = tid >> 5, lane = tid & 31;
    const int g    = (blockIdx.x >> 4) * 4 + wid;   // 0..255
    const int img  = g * 32 + lane;
    const float* xi = x + (size_t)img * 784;

    u64 acc[NCLS];
    #pragma unroll
    for (int c = 0; c < NCLS; ++c) acc[c] = 0ULL;

    for (int li = 0; li < np; ++li) {
        const int pa  = 2 * (ps + li);
        const int pr  = pa / 14;
        const int pc  = pa - pr * 14;            // even
        const int off = pr * 56 + pc * 2;        // 16B-aligned

        float4 vt = *reinterpret_cast<const float4*>(xi + off);      // pa:px0,px1 pb:px0,px1
        float4 vb = *reinterpret_cast<const float4*>(xi + off + 28); // pa:px2,px3 pb:px2,px3

        float c0a,s0a,c0b,s0b,c1a,s1a,c1b,s1b;
        float c2a,s2a,c2b,s2b,c3a,s3a,c3b,s3b;
        __sincosf(0.5f * vt.x, &s0a, &c0a);
        __sincosf(0.5f * vt.z, &s0b, &c0b);
        __sincosf(0.5f * vt.y, &s1a, &c1a);
        __sincosf(0.5f * vt.w, &s1b, &c1b);
        __sincosf(0.5f * vb.x, &s2a, &c2a);
        __sincosf(0.5f * vb.z, &s2b, &c2b);
        __sincosf(0.5f * vb.y, &s3a, &c3a);
        __sincosf(0.5f * vb.w, &s3b, &c3b);
        const u64 cx0 = pk2(c0a, c0b), sx0 = pk2(s0a, s0b);
        const u64 cx1 = pk2(c1a, c1b), sx1 = pk2(s1a, s1b);
        const u64 cx2 = pk2(c2a, c2b), sx2 = pk2(s2a, s2b);
        const u64 cx3 = pk2(c3a, c3b), sx3 = pk2(s3a, s3b);

        const ulonglong2* wrow = reinterpret_cast<const ulonglong2*>(&sWp[li * 100]);

        #pragma unroll
        for (int p = 0; p < NPROTO; ++p) {
            const ulonglong2 cyA = *reinterpret_cast<const ulonglong2*>(&sPc2[p * 4]);
            const ulonglong2 cyB = *reinterpret_cast<const ulonglong2*>(&sPc2[p * 4 + 2]);
            const ulonglong2 syA = *reinterpret_cast<const ulonglong2*>(&sPs2[p * 4]);
            const ulonglong2 syB = *reinterpret_cast<const ulonglong2*>(&sPs2[p * 4 + 2]);

            // cos((x-y)/2) = cos(x/2)cos(y/2) + sin(x/2)sin(y/2); packed (pa,pb)
            u64 t0 = fma2(cx0, cyA.x, mul2(sx0, syA.x));
            u64 t1 = fma2(cx1, cyA.y, mul2(sx1, syA.y));
            u64 t2 = fma2(cx2, cyB.x, mul2(sx2, syB.x));
            u64 t3 = fma2(cx3, cyB.y, mul2(sx3, syB.y));
            u64 kq = mul2(mul2(t0, t1), mul2(t2, t3)) & 0x7FFFFFFF7FFFFFFFULL;

            const ulonglong2* wp = wrow + p * 5;
            #pragma unroll
            for (int cc = 0; cc < 5; ++cc) {     // 2 classes per LDS.128
                ulonglong2 wv = wp[cc];
                acc[cc * 2    ] = fma2(kq, wv.x, acc[cc * 2    ]);
                acc[cc * 2 + 1] = fma2(kq, wv.y, acc[cc * 2 + 1]);
            }
        }
    }

    // collapse patch halves; coalesced store
    float* op = g_scratch + (size_t)(chunk * NGRP + g) * (NCLS * 32);
    #pragma unroll
    for (int c = 0; c < NCLS; ++c) {
        float2 f = up2(acc[c]);
        op[c * 32 + lane] = f.x + f.y;
    }
}

// ---------------------------------------------------------------------------
// Stage 2: 64 CTAs x 128, one thread per image. 160 coalesced loads (L2-hot
// scratch), bias + log_softmax, store.
// ---------------------------------------------------------------------------
__global__ void __launch_bounds__(128)
quanv_stage2(const float* __restrict__ bias, float* __restrict__ out)
{
    const int img  = blockIdx.x * 128 + threadIdx.x;
    const int g    = img >> 5;
    const int lane = img & 31;

    float logit[NCLS];
    #pragma unroll
    for (int c = 0; c < NCLS; ++c) logit[c] = bias[c];

    #pragma unroll
    for (int chunk = 0; chunk < NCHUNK; ++chunk) {
        const float* sp = g_scratch + (size_t)(chunk * NGRP + g) * (NCLS * 32);
        #pragma unroll
        for (int c = 0; c < NCLS; ++c)
            logit[c] += sp[c * 32 + lane];
    }

    float m = logit[0];
    #pragma unroll
    for (int c = 1; c < NCLS; ++c) m = fmaxf(m, logit[c]);
    float ssum = 0.f;
    #pragma unroll
    for (int c = 0; c < NCLS; ++c) ssum += expf(logit[c] - m);
    const float lse = m + logf(ssum);

    float* op = out + (size_t)img * NCLS;
    #pragma unroll
    for (int c = 0; c < NCLS; ++c) op[c] = logit[c] - lse;
}

// ---------------------------------------------------------------------------
extern "C" void kernel_launch(void* const* d_in, const int* in_sizes, int n_in,
                              void* d_out, int out_size)
{
    const float* x     = (const float*)d_in[0];  // (8192, 784)
    const float* proto = (const float*)d_in[1];  // (10, 4)
    const float* W     = (const float*)d_in[2];  // (10, 1960)
    const float* bias  = (const float*)d_in[3];  // (10,)
    float* out = (float*)d_out;                  // (8192, 10)

    quanv_stage1<<<NCHUNK * (NGRP / 4), 128>>>(x, proto, W);   // 1024 CTAs
    quanv_stage2<<<BIMG / 128, 128>>>(bias, out);              // 64 CTAs
}

// round 6
// speedup vs baseline: 1.2581x; 1.2581x over previous
#include <cuda_runtime.h>
#include <math.h>

#define NPROTO  10
#define NCLS    10
#define NPATCH  196
#define NFEAT   1960
#define BIMG    8192
#define NCHUNK  16
#define NGRP    128     // image groups of 64

typedef unsigned long long u64;

// scratch layout: [cls][chunk][img]  -> stage2 reads are coalesced + independent
__device__ float g_scratch[NCLS * NCHUNK * BIMG];   // 5.24 MB

// ---- packed f32x2 helpers ---------------------------------------------------
__device__ __forceinline__ u64 pk2(float lo, float hi) {
    u64 r; asm("mov.b64 %0, {%1,%2};" : "=l"(r) : "f"(lo), "f"(hi)); return r;
}
__device__ __forceinline__ u64 fma2(u64 a, u64 b, u64 c) {
    u64 d; asm("fma.rn.f32x2 %0, %1, %2, %3;" : "=l"(d) : "l"(a), "l"(b), "l"(c)); return d;
}
__device__ __forceinline__ u64 mul2(u64 a, u64 b) {
    u64 d; asm("mul.rn.f32x2 %0, %1, %2;" : "=l"(d) : "l"(a), "l"(b)); return d;
}
__device__ __forceinline__ float2 up2(u64 a) {
    float2 f; asm("mov.b64 {%0,%1}, %2;" : "=f"(f.x), "=f"(f.y) : "l"(a)); return f;
}

// ---------------------------------------------------------------------------
// Stage 1: 512 CTAs x 128 (4 warps). chunk = blockIdx & 15 (6-7 patch pairs),
// warp w -> image group (64 images); lane owns imgA = g*64+lane, imgB = +32.
// f32x2 lanes pack the patch pair (pa, pa+1); rp indexes the two images.
// W slice prepacked as (W[c,p,pa], W[c,p,pb]) u64 -> 5 LDS.128 per (pair,p),
// shared by both rp accumulators (2x amortization).
// ---------------------------------------------------------------------------
__global__ void __launch_bounds__(128, 4)
quanv_stage1(const float* __restrict__ x,
             const float* __restrict__ proto,
             const float* __restrict__ W)
{
    __shared__ __align__(16) u64 sWp[7 * NPROTO * NCLS];  // [li][p][c]
    __shared__ __align__(16) u64 sPc2[NPROTO * 4];        // dup (cy,cy)
    __shared__ __align__(16) u64 sPs2[NPROTO * 4];        // dup (sy,sy)

    const int tid   = threadIdx.x;
    const int chunk = blockIdx.x & 15;
    const int ps = chunk * 6 + min(chunk, 2);   // pair start
    const int np = 6 + (chunk < 2 ? 1 : 0);     // pair count

    for (int i = tid; i < np * 100; i += 128) {
        const int li = i / 100, rem = i - li * 100;
        const int p  = rem / 10, c = rem - p * 10;
        const int pa = 2 * (ps + li);
        float2 wv = *reinterpret_cast<const float2*>(W + c * NFEAT + p * NPATCH + pa);
        sWp[i] = pk2(wv.x, wv.y);
    }
    if (tid < NPROTO * 4) {
        float s, c; __sincosf(0.5f * proto[tid], &s, &c);
        sPc2[tid] = pk2(c, c);
        sPs2[tid] = pk2(s, s);
    }
    __syncthreads();

    const int wid  = tid >> 5, lane = tid & 31;
    const int g    = (blockIdx.x >> 4) * 4 + wid;    // 0..127
    const int imgA = g * 64 + lane;

    const float* x0 = x + (size_t)imgA * 784;
    const float* x1 = x + (size_t)(imgA + 32) * 784;

    u64 acc[2][NCLS];
    #pragma unroll
    for (int rp = 0; rp < 2; ++rp)
        #pragma unroll
        for (int c = 0; c < NCLS; ++c) acc[rp][c] = 0ULL;

    #pragma unroll 2
    for (int li = 0; li < np; ++li) {
        const int pa  = 2 * (ps + li);
        const int pr  = pa / 14;
        const int pc  = pa - pr * 14;            // even
        const int off = pr * 56 + pc * 2;        // 16B-aligned float index

        u64 cxp[2][4], sxp[2][4];
        const float* xr[2] = { x0, x1 };
        #pragma unroll
        for (int rp = 0; rp < 2; ++rp) {
            float4 vt = *reinterpret_cast<const float4*>(xr[rp] + off);      // pa/pb top row
            float4 vb = *reinterpret_cast<const float4*>(xr[rp] + off + 28); // pa/pb bottom row
            float c0a,s0a,c0b,s0b,c1a,s1a,c1b,s1b;
            float c2a,s2a,c2b,s2b,c3a,s3a,c3b,s3b;
            __sincosf(0.5f * vt.x, &s0a, &c0a);
            __sincosf(0.5f * vt.z, &s0b, &c0b);
            __sincosf(0.5f * vt.y, &s1a, &c1a);
            __sincosf(0.5f * vt.w, &s1b, &c1b);
            __sincosf(0.5f * vb.x, &s2a, &c2a);
            __sincosf(0.5f * vb.z, &s2b, &c2b);
            __sincosf(0.5f * vb.y, &s3a, &c3a);
            __sincosf(0.5f * vb.w, &s3b, &c3b);
            cxp[rp][0] = pk2(c0a, c0b);  sxp[rp][0] = pk2(s0a, s0b);
            cxp[rp][1] = pk2(c1a, c1b);  sxp[rp][1] = pk2(s1a, s1b);
            cxp[rp][2] = pk2(c2a, c2b);  sxp[rp][2] = pk2(s2a, s2b);
            cxp[rp][3] = pk2(c3a, c3b);  sxp[rp][3] = pk2(s3a, s3b);
        }

        const ulonglong2* wrow = reinterpret_cast<const ulonglong2*>(&sWp[li * 100]);

        #pragma unroll
        for (int p = 0; p < NPROTO; ++p) {
            const ulonglong2 cyA = *reinterpret_cast<const ulonglong2*>(&sPc2[p * 4]);
            const ulonglong2 cyB = *reinterpret_cast<const ulonglong2*>(&sPc2[p * 4 + 2]);
            const ulonglong2 syA = *reinterpret_cast<const ulonglong2*>(&sPs2[p * 4]);
            const ulonglong2 syB = *reinterpret_cast<const ulonglong2*>(&sPs2[p * 4 + 2]);

            u64 kq[2];
            #pragma unroll
            for (int rp = 0; rp < 2; ++rp) {
                // cos((x-y)/2) = cos(x/2)cos(y/2) + sin(x/2)sin(y/2); packed (pa,pb)
                u64 t0 = fma2(cxp[rp][0], cyA.x, mul2(sxp[rp][0], syA.x));
                u64 t1 = fma2(cxp[rp][1], cyA.y, mul2(sxp[rp][1], syA.y));
                u64 t2 = fma2(cxp[rp][2], cyB.x, mul2(sxp[rp][2], syB.x));
                u64 t3 = fma2(cxp[rp][3], cyB.y, mul2(sxp[rp][3], syB.y));
                kq[rp] = mul2(mul2(t0, t1), mul2(t2, t3)) & 0x7FFFFFFF7FFFFFFFULL;
            }

            const ulonglong2* wp = wrow + p * 5;
            #pragma unroll
            for (int cc = 0; cc < 5; ++cc) {       // one LDS.128 feeds 4 FFMA2
                ulonglong2 wv = wp[cc];
                acc[0][cc*2  ] = fma2(kq[0], wv.x, acc[0][cc*2  ]);
                acc[1][cc*2  ] = fma2(kq[1], wv.x, acc[1][cc*2  ]);
                acc[0][cc*2+1] = fma2(kq[0], wv.y, acc[0][cc*2+1]);
                acc[1][cc*2+1] = fma2(kq[1], wv.y, acc[1][cc*2+1]);
            }
        }
    }

    // collapse patch halves; store to [cls][chunk][img] (coalesced per rp)
    #pragma unroll
    for (int c = 0; c < NCLS; ++c) {
        float2 f0 = up2(acc[0][c]);
        float2 f1 = up2(acc[1][c]);
        float* base = g_scratch + ((size_t)c * NCHUNK + chunk) * BIMG + g * 64;
        base[lane     ] = f0.x + f0.y;
        base[lane + 32] = f1.x + f1.y;
    }
}

// ---------------------------------------------------------------------------
// Stage 2: 64 CTAs x 128, one thread per image. 160 coalesced *independent*
// LDGs (scratch is [cls][chunk][img]) -> MLP ~30; bias + log_softmax.
// ---------------------------------------------------------------------------
__global__ void __launch_bounds__(128)
quanv_stage2(const float* __restrict__ bias, float* __restrict__ out)
{
    const int img = blockIdx.x * 128 + threadIdx.x;

    float logit[NCLS];
    #pragma unroll
    for (int c = 0; c < NCLS; ++c) logit[c] = bias[c];

    #pragma unroll
    for (int c = 0; c < NCLS; ++c) {
        const float* sp = g_scratch + (size_t)c * NCHUNK * BIMG + img;
        float s0 = 0.f, s1 = 0.f, s2 = 0.f, s3 = 0.f;
        #pragma unroll
        for (int ch = 0; ch < NCHUNK; ch += 4) {
            s0 += sp[(ch    ) * BIMG];
            s1 += sp[(ch + 1) * BIMG];
            s2 += sp[(ch + 2) * BIMG];
            s3 += sp[(ch + 3) * BIMG];
        }
        logit[c] += (s0 + s1) + (s2 + s3);
    }

    float m = logit[0];
    #pragma unroll
    for (int c = 1; c < NCLS; ++c) m = fmaxf(m, logit[c]);
    float ssum = 0.f;
    #pragma unroll
    for (int c = 0; c < NCLS; ++c) ssum += expf(logit[c] - m);
    const float lse = m + logf(ssum);

    float* op = out + (size_t)img * NCLS;
    #pragma unroll
    for (int c = 0; c < NCLS; ++c) op[c] = logit[c] - lse;
}

// ---------------------------------------------------------------------------
extern "C" void kernel_launch(void* const* d_in, const int* in_sizes, int n_in,
                              void* d_out, int out_size)
{
    const float* x     = (const float*)d_in[0];  // (8192, 784)
    const float* proto = (const float*)d_in[1];  // (10, 4)
    const float* W     = (const float*)d_in[2];  // (10, 1960)
    const float* bias  = (const float*)d_in[3];  // (10,)
    float* out = (float*)d_out;                  // (8192, 10)

    // 32 group-quads x 16 chunks = 512 CTAs x 128 threads
    quanv_stage1<<<(NGRP / 4) * NCHUNK, 128>>>(x, proto, W);
    quanv_stage2<<<BIMG / 128, 128>>>(bias, out);
}